// round 1
// baseline (speedup 1.0000x reference)
#include <cuda_runtime.h>
#include <math.h>

#define Bq 4
#define Wd 2048
#define DM 256
#define DI 512
#define DS 16
#define DR 16
#define NROW (Bq*Wd)   // 8192

// ---------------- static scratch (no allocation allowed) ----------------
__device__ float g_u[NROW*DM];        // rms-normed input
__device__ float g_xz[NROW*2*DI];     // in_proj output
__device__ float g_xs[NROW*DI];       // conv+silu output (u for scan)
__device__ float g_dbc[NROW*48];      // x_proj output (dt_rank + 2*D_STATE)
__device__ float g_delta[NROW*DI];    // softplus(dt)
__device__ float g_y[NROW*DI];        // scan output
__device__ float g_yg[NROW*DI];       // gated y

// ---------------- embed: h = x*emb_w + emb_b ----------------
__global__ void k_embed(const float* __restrict__ x, const float* __restrict__ ew,
                        const float* __restrict__ eb, float* __restrict__ h) {
    int r = blockIdx.x, d = threadIdx.x;
    h[r*DM + d] = fmaf(x[r], ew[d], eb[d]);
}

// ---------------- rmsnorm -> g_u ----------------
__global__ void k_rmsnorm(const float* __restrict__ h, const float* __restrict__ w) {
    int r = blockIdx.x, d = threadIdx.x;
    float v = h[r*DM + d];
    float ss = v*v;
    #pragma unroll
    for (int o = 16; o; o >>= 1) ss += __shfl_xor_sync(0xffffffffu, ss, o);
    __shared__ float sh[8];
    int wid = d >> 5, lane = d & 31;
    if (lane == 0) sh[wid] = ss;
    __syncthreads();
    if (wid == 0) {
        float t = (lane < 8) ? sh[lane] : 0.f;
        #pragma unroll
        for (int o = 4; o; o >>= 1) t += __shfl_xor_sync(0xffffffffu, t, o);
        if (lane == 0) sh[0] = t;
    }
    __syncthreads();
    float inv = rsqrtf(sh[0] * (1.0f/DM) + 1e-5f);
    g_u[r*DM + d] = v * inv * w[d];
}

// ---------------- SGEMM: C[m,n] (+)= sum_k A[m,k]*Wt[n,k] ----------------
template<int BM, int BN, int BK, int TM, int TN, bool ACC>
__global__ __launch_bounds__(256) void k_sgemm_nt(
    const float* __restrict__ A, const float* __restrict__ Wt,
    float* __restrict__ C, int M, int N, int K)
{
    __shared__ float As[BK][BM+4];
    __shared__ float Bs[BK][BN+4];
    const int tid = threadIdx.x;
    const int tc = tid % (BN/TN);
    const int tr = tid / (BN/TN);
    const int m0 = blockIdx.y * BM, n0 = blockIdx.x * BN;

    float acc[TM][TN];
    #pragma unroll
    for (int i = 0; i < TM; i++)
        #pragma unroll
        for (int j = 0; j < TN; j++) acc[i][j] = 0.f;

    for (int k0 = 0; k0 < K; k0 += BK) {
        #pragma unroll
        for (int i = 0; i < (BM*BK)/(256*4); ++i) {
            int idx = tid + 256*i;
            int m = idx / (BK/4);
            int k4 = idx % (BK/4);
            float4 v = *(const float4*)&A[(size_t)(m0+m)*K + k0 + k4*4];
            As[k4*4+0][m] = v.x; As[k4*4+1][m] = v.y;
            As[k4*4+2][m] = v.z; As[k4*4+3][m] = v.w;
        }
        #pragma unroll
        for (int i = 0; i < (BN*BK)/(256*4); ++i) {
            int idx = tid + 256*i;
            int n = idx / (BK/4);
            int k4 = idx % (BK/4);
            float4 v = *(const float4*)&Wt[(size_t)(n0+n)*K + k0 + k4*4];
            Bs[k4*4+0][n] = v.x; Bs[k4*4+1][n] = v.y;
            Bs[k4*4+2][n] = v.z; Bs[k4*4+3][n] = v.w;
        }
        __syncthreads();
        #pragma unroll
        for (int kk = 0; kk < BK; ++kk) {
            float a[TM], b[TN];
            #pragma unroll
            for (int i = 0; i < TM; i++) a[i] = As[kk][tr*TM + i];
            #pragma unroll
            for (int j = 0; j < TN; j++) b[j] = Bs[kk][tc*TN + j];
            #pragma unroll
            for (int i = 0; i < TM; i++)
                #pragma unroll
                for (int j = 0; j < TN; j++)
                    acc[i][j] = fmaf(a[i], b[j], acc[i][j]);
        }
        __syncthreads();
    }
    #pragma unroll
    for (int i = 0; i < TM; i++)
        #pragma unroll
        for (int j = 0; j < TN; j++) {
            size_t idx = (size_t)(m0 + tr*TM + i)*N + n0 + tc*TN + j;
            if (ACC) C[idx] += acc[i][j]; else C[idx] = acc[i][j];
        }
}

// ---------------- causal depthwise conv (k=4) + silu -> g_xs ----------------
__global__ void k_conv(const float* __restrict__ cw, const float* __restrict__ cb) {
    int idx = blockIdx.x * blockDim.x + threadIdx.x;   // NROW*DI
    int e = idx % DI;
    int row = idx / DI;        // b*W + w
    int w = row % Wd;
    float acc = cb[e];
    #pragma unroll
    for (int k = 0; k < 4; k++) {
        int ww = w + k - 3;
        if (ww >= 0) acc = fmaf(cw[e*4 + k], g_xz[(size_t)(row + k - 3)*(2*DI) + e], acc);
    }
    g_xs[idx] = acc / (1.f + __expf(-acc));
}

// ---------------- x_proj: dbc[r,j] = sum_e xs[r,e]*xpw[j,e], j<48 ----------------
__global__ __launch_bounds__(256) void k_xproj(const float* __restrict__ xpw) {
    __shared__ float sx[8][DI];               // 16 KB
    int r0 = blockIdx.x * 8;
    #pragma unroll
    for (int i = 0; i < 4; i++) {
        int idx = threadIdx.x + 256*i;        // float4 index
        int rr = idx / (DI/4);
        int c4 = idx % (DI/4);
        *(float4*)&sx[rr][c4*4] = *(const float4*)&g_xs[(size_t)(r0+rr)*DI + c4*4];
    }
    __syncthreads();
    int warp = threadIdx.x >> 5, lane = threadIdx.x & 31;
    for (int jj = 0; jj < 6; jj++) {
        int j = warp*6 + jj;
        float wreg[16];
        #pragma unroll
        for (int i = 0; i < 16; i++) wreg[i] = xpw[(size_t)j*DI + lane + 32*i];
        #pragma unroll
        for (int rr = 0; rr < 8; rr++) {
            float s = 0.f;
            #pragma unroll
            for (int i = 0; i < 16; i++) s = fmaf(wreg[i], sx[rr][lane + 32*i], s);
            #pragma unroll
            for (int o = 16; o; o >>= 1) s += __shfl_xor_sync(0xffffffffu, s, o);
            if (lane == 0) g_dbc[(size_t)(r0+rr)*48 + j] = s;
        }
    }
}

// ---------------- dt_proj + softplus -> g_delta ----------------
__global__ void k_dt(const float* __restrict__ dtw, const float* __restrict__ dtb) {
    int r = blockIdx.x, d = threadIdx.x;   // 512 threads
    __shared__ float sd[DR];
    if (d < DR) sd[d] = g_dbc[(size_t)r*48 + d];
    __syncthreads();
    float acc = dtb[d];
    #pragma unroll
    for (int j = 0; j < DR; j++) acc = fmaf(sd[j], dtw[d*DR + j], acc);
    float sp = fmaxf(acc, 0.f) + log1pf(__expf(-fabsf(acc)));
    g_delta[(size_t)r*DI + d] = sp;
}

// ---------------- selective scan: warp handles 2 d-channels ----------------
__global__ __launch_bounds__(128) void k_scan(const float* __restrict__ A_log,
                                              const float* __restrict__ Dp) {
    int gw = (blockIdx.x * blockDim.x + threadIdx.x) >> 5;  // global warp
    int lane = threadIdx.x & 31;
    int b = gw >> 8;                 // / (DI/2)
    int dpair = gw & 255;
    int s = lane & 15;
    int dd = dpair*2 + (lane >> 4);

    float Av = -expf(A_log[dd*DS + s]);
    float Dpv = Dp[dd];
    float hst = 0.f;

    const float* pd = g_delta + (size_t)b*Wd*DI + dd;
    const float* pu = g_xs    + (size_t)b*Wd*DI + dd;
    const float* pB = g_dbc   + (size_t)b*Wd*48 + DR + s;
    const float* pC = g_dbc   + (size_t)b*Wd*48 + DR + DS + s;
    float* py = g_y + (size_t)b*Wd*DI + dd;

    float dlt = pd[0], uu = pu[0], Bv = pB[0], Cv = pC[0];
    for (int t = 0; t < Wd; t++) {
        float dc = dlt, uc = uu, Bc = Bv, Cc = Cv;
        if (t + 1 < Wd) {                     // prefetch next step
            dlt = pd[(size_t)(t+1)*DI];
            uu  = pu[(size_t)(t+1)*DI];
            Bv  = pB[(size_t)(t+1)*48];
            Cv  = pC[(size_t)(t+1)*48];
        }
        float dA = __expf(dc * Av);
        hst = fmaf(dA, hst, dc * Bc * uc);
        float yv = hst * Cc;
        yv += __shfl_xor_sync(0xffffffffu, yv, 8);
        yv += __shfl_xor_sync(0xffffffffu, yv, 4);
        yv += __shfl_xor_sync(0xffffffffu, yv, 2);
        yv += __shfl_xor_sync(0xffffffffu, yv, 1);
        if (s == 0) py[(size_t)t*DI] = fmaf(uc, Dpv, yv);
    }
}

// ---------------- gate: yg = y * silu(z) ----------------
__global__ void k_gate() {
    int idx = blockIdx.x * blockDim.x + threadIdx.x;  // NROW*DI
    int r = idx / DI, e = idx % DI;
    float z = g_xz[(size_t)r*(2*DI) + DI + e];
    g_yg[idx] = g_y[idx] * z / (1.f + __expf(-z));
}

// ---------------- host launch ----------------
extern "C" void kernel_launch(void* const* d_in, const int* in_sizes, int n_in,
                              void* d_out, int out_size) {
    const float* x         = (const float*)d_in[0];
    const float* emb_w     = (const float*)d_in[1];
    const float* emb_b     = (const float*)d_in[2];
    const float* in_proj_w = (const float*)d_in[3];
    const float* conv_w    = (const float*)d_in[4];
    const float* conv_b    = (const float*)d_in[5];
    const float* x_proj_w  = (const float*)d_in[6];
    const float* dt_proj_w = (const float*)d_in[7];
    const float* dt_proj_b = (const float*)d_in[8];
    const float* A_log     = (const float*)d_in[9];
    const float* Dp        = (const float*)d_in[10];
    const float* out_proj_w= (const float*)d_in[11];
    const float* norm_w    = (const float*)d_in[12];
    float* h = (float*)d_out;

    float *p_u, *p_xz, *p_yg;
    cudaGetSymbolAddress((void**)&p_u,  g_u);
    cudaGetSymbolAddress((void**)&p_xz, g_xz);
    cudaGetSymbolAddress((void**)&p_yg, g_yg);

    k_embed<<<NROW, DM>>>(x, emb_w, emb_b, h);

    for (int l = 0; l < 2; ++l) {
        const float* inw = in_proj_w + (size_t)l * (2*DI) * DM;
        const float* cw  = conv_w   + (size_t)l * DI * 4;
        const float* cb  = conv_b   + (size_t)l * DI;
        const float* xpw = x_proj_w + (size_t)l * 48 * DI;
        const float* dtw = dt_proj_w+ (size_t)l * DI * DR;
        const float* dtb = dt_proj_b+ (size_t)l * DI;
        const float* al  = A_log    + (size_t)l * DI * DS;
        const float* dp  = Dp       + (size_t)l * DI;
        const float* ow  = out_proj_w + (size_t)l * DM * DI;
        const float* nw  = norm_w   + (size_t)l * DM;

        k_rmsnorm<<<NROW, DM>>>(h, nw);

        // xz = u @ in_w^T : M=8192, N=1024, K=256
        {
            dim3 grid((2*DI)/64, NROW/128);
            k_sgemm_nt<128,64,16,8,4,false><<<grid, 256>>>(p_u, inw, p_xz, NROW, 2*DI, DM);
        }

        k_conv<<<(NROW*DI)/256, 256>>>(cw, cb);

        k_xproj<<<NROW/8, 256>>>(xpw);

        k_dt<<<NROW, DI>>>(dtw, dtb);

        k_scan<<<(Bq*(DI/2)*32)/128, 128>>>(al, dp);

        k_gate<<<(NROW*DI)/256, 256>>>();

        // h += yg @ ow^T : M=8192, N=256, K=512
        {
            dim3 grid(DM/64, NROW/128);
            k_sgemm_nt<128,64,16,8,4,true><<<grid, 256>>>(p_yg, ow, h, NROW, DM, DI);
        }
    }
}